// round 14
// baseline (speedup 1.0000x reference)
#include <cuda_runtime.h>
#include <math.h>
#include <stdint.h>

#define THREADS 256
#define FULLM 0xFFFFFFFFu

// ---------------- layer tables ----------------
__constant__ int c_H[5]        = {480, 240, 120, 60, 30};
__constant__ int c_chanBase[5] = {0, 64, 192, 448, 960};
__constant__ int c_C[5]        = {64, 128, 256, 512, 512};
__constant__ int c_procBase[5] = {0, 230400, 288000, 302400, 306000};

// ---------------- scratch (device globals; no allocation) ----------------
__device__ unsigned g_cmax[1472];        // raw bits of per-channel max (values >= 0)
__device__ unsigned g_cnt[1472];         // tiles-arrived counter per channel
__device__ int      g_hist[1472][12];    // [0:6) histc bins, [6:12) gidx bins
__device__ float    g_lut[1472][6];      // per-channel contribution LUT
__device__ float    g_S5[5];             // sum_c lut_c[5] per layer
__device__ float    g_bord[5];           // border proc value per layer
__device__ unsigned g_rarecnt;
__device__ unsigned g_rare[28108800];    // packed rare records: pix|ch<<18|b2<<29
__device__ float    g_proc[306900];      // corrections (zeroed), then full proc values
__device__ unsigned g_pstat[5][2];       // proc min/max per layer (encoded)
__device__ float    g_group[5][57600];   // resized+thresholded maps
__device__ unsigned g_gstat[5][2];       // group min/max per layer (encoded)

// ---------------- float <-> orderable uint ----------------
__device__ __forceinline__ unsigned fenc(float f) {
    unsigned b = __float_as_uint(f);
    return (b & 0x80000000u) ? ~b : (b | 0x80000000u);
}
__device__ __forceinline__ float fdec(unsigned u) {
    unsigned b = (u & 0x80000000u) ? (u & 0x7FFFFFFFu) : ~u;
    return __uint_as_float(b);
}

__device__ __forceinline__ void blockMinMax(float vmn, float vmx, unsigned* stat, float* s) {
#pragma unroll
    for (int o = 16; o; o >>= 1) {
        vmn = fminf(vmn, __shfl_xor_sync(FULLM, vmn, o));
        vmx = fmaxf(vmx, __shfl_xor_sync(FULLM, vmx, o));
    }
    int w = threadIdx.x >> 5;
    if ((threadIdx.x & 31) == 0) { s[w] = vmn; s[8 + w] = vmx; }
    __syncthreads();
    if (threadIdx.x == 0) {
        float a = s[0], b = s[8];
#pragma unroll
        for (int i = 1; i < 8; i++) { a = fminf(a, s[i]); b = fmaxf(b, s[8 + i]); }
        atomicMin(&stat[0], fenc(a));
        atomicMax(&stat[1], fenc(b));
    }
    __syncthreads();
}

// ---------------- pass 0: init ----------------
__global__ void __launch_bounds__(THREADS) k_init() {
    int i = blockIdx.x * THREADS + threadIdx.x;
    if (i < 306900) g_proc[i] = 0.f;          // correction buffer starts zeroed
    if (i < 1472 * 12) ((int*)g_hist)[i] = 0;
    if (i < 1472) { g_cmax[i] = 0u; g_cnt[i] = 0u; }
    if (i == 0) g_rarecnt = 0u;
    if (i < 5) {
        g_pstat[i][0] = 0xFFFFFFFFu; g_pstat[i][1] = 0u;
        g_gstat[i][0] = 0xFFFFFFFFu; g_gstat[i][1] = 0u;
    }
}

// ---------------- fused max+hist, two channel-units per block ----------------
// per layer (channels x tiles, paired across channel halves):
//   L0: 64x32 -> 1024 blocks (pair c, c+32)   L1: 128x8 -> 512 (pair c, c+64)
//   L2: 256x2 -> 256 (pair c, c+128)          L3: 512x1 -> 256 (pair c, c+256)
//   L4: 512x1 -> 256 (pair c, c+256, scalar)  total 2304 blocks

__device__ __forceinline__ void hist_flush1(unsigned long long h1, int ch) {
#pragma unroll
    for (int j = 0; j < 6; j++) {
        int c1 = (int)((h1 >> (j * 10)) & 1023u);
        c1 = __reduce_add_sync(FULLM, c1);
        if ((threadIdx.x & 31) == 0 && c1) atomicAdd(&g_hist[ch][j], c1);
    }
}

__device__ __forceinline__ void emit4(unsigned msk, const unsigned* rec, const int* b2, int ch) {
    unsigned any = __ballot_sync(FULLM, msk != 0);
    if (!any) return;
    unsigned lane = threadIdx.x & 31;
    int cnt = __popc(msk);
    int pre = cnt;
#pragma unroll
    for (int o = 1; o < 32; o <<= 1) {
        int t = __shfl_up_sync(FULLM, pre, o);
        if (lane >= o) pre += t;
    }
    int tot = __shfl_sync(FULLM, pre, 31);
    unsigned bs = 0;
    if (lane == 31) bs = atomicAdd(&g_rarecnt, (unsigned)tot);
    bs = __shfl_sync(FULLM, bs, 31);
    unsigned off = bs + (unsigned)(pre - cnt);
#pragma unroll
    for (int k = 0; k < 4; k++) {
        if ((msk >> k) & 1u) {
            g_rare[off++] = rec[k];
            atomicAdd(&g_hist[ch][6 + b2[k]], 1);
        }
    }
}

// block-reduce max, publish to channel, bump arrival counter (non-blocking)
__device__ __forceinline__ void arrive_chmax(float mx, int ch, float* sred) {
#pragma unroll
    for (int o = 16; o; o >>= 1) mx = fmaxf(mx, __shfl_xor_sync(FULLM, mx, o));
    if ((threadIdx.x & 31) == 0) sred[threadIdx.x >> 5] = mx;
    __syncthreads();
    if (threadIdx.x == 0) {
        float a = sred[0];
#pragma unroll
        for (int i = 1; i < 8; i++) a = fmaxf(a, sred[i]);
        atomicMax(&g_cmax[ch], __float_as_uint(a));   // nonneg floats: raw-bit monotonic
        __threadfence();
        atomicAdd(&g_cnt[ch], 1u);
    }
    __syncthreads();
}

// wait until all NT tiles of the channel arrived, then read the final max
template <int NT>
__device__ __forceinline__ float wait_chmax(int ch, float* smx) {
    if (threadIdx.x == 0) {
        if (NT > 1) {
            while (*(volatile unsigned*)&g_cnt[ch] < (unsigned)NT) __nanosleep(64);
            __threadfence();
        }
        *smx = __uint_as_float(*(volatile unsigned*)&g_cmax[ch]);
    }
    __syncthreads();
    return *smx;
}

// phase 1: stream tile, return thread-local max
template <int H, int T>
__device__ __forceinline__ float ph1v(const float* __restrict__ base, int tile) {
    constexpr int W = H, F4 = W / 4;
    int rowsThis = (H - 2 - tile + T - 1) / T;
    int total = rowsThis * F4;
    float mx = 0.f;
#pragma unroll 4
    for (int i = threadIdx.x; i < total; i += THREADS) {
        int m = i / F4, j = i - m * F4;
        int r = 1 + tile + m * T;
        float4 v = *(const float4*)(base + r * W + 4 * j);
        if (j == 0) v.x = 0.f;
        if (j == F4 - 1) v.w = 0.f;
        mx = fmaxf(mx, fmaxf(fmaxf(v.x, v.y), fmaxf(v.z, v.w)));
    }
    return mx;
}

// phase 2: re-read tile, histogram + rare emission
template <int H, int T>
__device__ void ph2v(const float* __restrict__ base, int tile, int ch, float mxc) {
    constexpr int W = H, F4 = W / 4;
    float s = (mxc > 0.f) ? __fdiv_rn(1536.f, mxc) : 0.f;
    unsigned long long h1 = 0ULL;
    int rowsThis = (H - 2 - tile + T - 1) / T;
    int total = rowsThis * F4;
    int iters = (total + THREADS - 1) / THREADS;
    for (int it = 0; it < iters; it++) {
        int i = it * THREADS + threadIdx.x;
        bool ok = i < total;
        int ii = ok ? i : 0;
        int m = ii / F4, j = ii - m * F4;
        int r = 1 + tile + m * T;
        float4 v = ok ? *(const float4*)(base + r * W + 4 * j)
                      : make_float4(1e30f, 1e30f, 1e30f, 1e30f);
        if (ok) {
            if (j == 0) v.x = 0.f;
            if (j == F4 - 1) v.w = 0.f;
        }
        int i1[4];
        i1[0] = __float2int_rd(__fmul_rn(v.x, s));
        i1[1] = __float2int_rd(__fmul_rn(v.y, s));
        i1[2] = __float2int_rd(__fmul_rn(v.z, s));
        i1[3] = __float2int_rd(__fmul_rn(v.w, s));
        if (ok) {
#pragma unroll
            for (int k = 0; k < 4; k++) h1 += 1ULL << (min(i1[k] >> 8, 5) * 10);
        }
        unsigned pix = (unsigned)(r * W + 4 * j);
        unsigned msk = 0;
        unsigned rec[4]; int b2a[4];
        if (ok) {
#pragma unroll
            for (int k = 0; k < 4; k++) {
                bool rr = (i1[k] < 6);
                if (k == 0) rr = rr && (j != 0);          // border col 0: analytic
                if (k == 3) rr = rr && (j != F4 - 1);     // border col W-1: analytic
                int b2 = max(i1[k] - 1, 0);
                b2a[k] = b2;
                rec[k] = (pix + k) | ((unsigned)ch << 18) | ((unsigned)b2 << 29);
                if (rr) msk |= 1u << k;
            }
        }
        emit4(msk, rec, b2a, ch);
    }
    hist_flush1(h1, ch);
    if (tile == 0 && threadIdx.x == 0) {
        atomicAdd(&g_hist[ch][0], 2 * W);                 // rows 0,H-1 -> histc bin 0
        atomicAdd(&g_hist[ch][6 + 0], 2 * (H + W) - 4);   // full border -> gidx bin 0
    }
}

template <int H, int T, int NT>
__device__ void fused_pair(const float* __restrict__ baseA, int chA,
                           const float* __restrict__ baseB, int chB,
                           int tile, float* sred, float* smx) {
    float mA = ph1v<H, T>(baseA, tile);
    arrive_chmax(mA, chA, sred);
    float mB = ph1v<H, T>(baseB, tile);
    arrive_chmax(mB, chB, sred);
    float MA = wait_chmax<NT>(chA, smx);      // overlapped with B's phase 1
    ph2v<H, T>(baseA, tile, chA, MA);
    float MB = wait_chmax<NT>(chB, smx);
    ph2v<H, T>(baseB, tile, chB, MB);
}

// scalar variant (layer 4, W=30)
template <int H>
__device__ float ph1s(const float* __restrict__ base) {
    constexpr int W = H, IW = W - 2, NI = IW * (H - 2);
    float mx = 0.f;
    for (int i = threadIdx.x; i < NI; i += THREADS) {
        int q = i / IW, col = i - q * IW;
        mx = fmaxf(mx, base[(q + 1) * W + col + 1]);
    }
    return mx;
}
template <int H>
__device__ void ph2s(const float* __restrict__ base, int ch, float mxc) {
    constexpr int W = H, IW = W - 2, NI = IW * (H - 2);
    float s = (mxc > 0.f) ? __fdiv_rn(1536.f, mxc) : 0.f;
    unsigned long long h1 = 0ULL;
    int iters = (NI + THREADS - 1) / THREADS;
    for (int it = 0; it < iters; it++) {
        int i = it * THREADS + threadIdx.x;
        bool ok = i < NI;
        int ii = ok ? i : 0;
        int q = ii / IW, col = ii - q * IW;
        int pix = (q + 1) * W + col + 1;
        float v = ok ? base[pix] : 1e30f;
        int i1 = __float2int_rd(__fmul_rn(v, s));
        if (ok) h1 += 1ULL << (min(i1 >> 8, 5) * 10);
        unsigned msk = (ok && i1 < 6) ? 1u : 0u;
        int b2 = max(i1 - 1, 0);
        unsigned rec[4]; int b2a[4];
        rec[0] = (unsigned)pix | ((unsigned)ch << 18) | ((unsigned)b2 << 29);
        b2a[0] = b2;
        rec[1] = rec[2] = rec[3] = 0; b2a[1] = b2a[2] = b2a[3] = 0;
        emit4(msk, rec, b2a, ch);
    }
    hist_flush1(h1, ch);
    if (threadIdx.x == 0) {
        int Nb = 2 * (H + W) - 4;
        atomicAdd(&g_hist[ch][0], Nb);
        atomicAdd(&g_hist[ch][6 + 0], Nb);
    }
}

__global__ void __launch_bounds__(THREADS) k_maxhist(const float* __restrict__ p0, const float* __restrict__ p1,
                                                     const float* __restrict__ p2, const float* __restrict__ p3,
                                                     const float* __restrict__ p4) {
    __shared__ float sred[8];
    __shared__ float smx;
    int b = blockIdx.x;
    if (b < 1024) {
        int c = b >> 5, tile = b & 31;                 // pair (c, c+32), 32 tiles each
        fused_pair<480, 32, 32>(p0 + (long long)c * 230400, c,
                                p0 + (long long)(c + 32) * 230400, c + 32, tile, sred, &smx);
    } else if (b < 1536) {
        int t = b - 1024, c = t >> 3, tile = t & 7;    // pair (c, c+64), 8 tiles
        fused_pair<240, 8, 8>(p1 + (long long)c * 57600, 64 + c,
                              p1 + (long long)(c + 64) * 57600, 64 + c + 64, tile, sred, &smx);
    } else if (b < 1792) {
        int t = b - 1536, c = t >> 1, tile = t & 1;    // pair (c, c+128), 2 tiles
        fused_pair<120, 2, 2>(p2 + (long long)c * 14400, 192 + c,
                              p2 + (long long)(c + 128) * 14400, 192 + c + 128, tile, sred, &smx);
    } else if (b < 2048) {
        int c = b - 1792;                              // pair (c, c+256), 1 tile
        fused_pair<60, 1, 1>(p3 + (long long)c * 3600, 448 + c,
                             p3 + (long long)(c + 256) * 3600, 448 + c + 256, 0, sred, &smx);
    } else {
        int c = b - 2048;                              // scalar pair (c, c+256)
        float mA = ph1s<30>(p4 + (long long)c * 900);
        arrive_chmax(mA, 960 + c, sred);
        float mB = ph1s<30>(p4 + (long long)(c + 256) * 900);
        arrive_chmax(mB, 960 + c + 256, sred);
        float MA = wait_chmax<1>(960 + c, &smx);
        ph2s<30>(p4 + (long long)c * 900, 960 + c, MA);
        float MB = wait_chmax<1>(960 + c + 256, &smx);
        ph2s<30>(p4 + (long long)(c + 256) * 900, 960 + c + 256, MB);
    }
}

// ---------------- pass LUT+S5: per-channel LUT, then per-layer S5/bord ----------------
__global__ void __launch_bounds__(THREADS) k_lut_s5() {
    __shared__ float sh[THREADS];
    __shared__ float sbord;
    int l = blockIdx.x;
    int C = c_C[l], cb = c_chanBase[l];
    int H = c_H[l], W = H, HW = H * W;
    float Nf = (float)HW;
    float s5part = 0.f;
    for (int c = threadIdx.x; c < C; c += THREADS) {
        int ch = cb + c;
        int gg[6], sg = 0;
#pragma unroll
        for (int j = 0; j < 5; j++) { gg[j] = g_hist[ch][6 + j]; sg += gg[j]; }
        gg[5] = HW - sg;                      // all non-rare interior pixels have gidx 5

        float hv[6];
#pragma unroll
        for (int j = 0; j < 6; j++)
            hv[j] = -logf(__fdiv_rn((float)g_hist[ch][j], Nf) + 1e-4f);

        float minv = 1e30f, maxv = -1e30f;
#pragma unroll
        for (int j = 0; j < 6; j++)
            if (gg[j] > 0) { minv = fminf(minv, hv[j]); maxv = fmaxf(maxv, hv[j]); }
        float rh = maxv - minv;

        const int jb = 0;                      // border pixels (value 0) -> gidx bin 0
        bool first = (c == 0);                 // channel 0 keeps its border in the map

        float lut[6] = {0.f, 0.f, 0.f, 0.f, 0.f, 0.f};
        if (rh > 0.f) {
            float dn[6];
#pragma unroll
            for (int j = 0; j < 6; j++)
                dn[j] = (gg[j] > 0) ? __fdiv_rn(hv[j] - minv, rh) : 0.f;
            float meandn = 0.f;
#pragma unroll
            for (int j = 0; j < 6; j++) meandn += (float)gg[j] * dn[j];
            meandn = __fdiv_rn(meandn, Nf);
            float w1 = 1.f - meandn; w1 *= w1;     // (max_dst - mean_dst)^2
            int Nb = 2 * (H + W) - 4;
            float mean_m = 0.f;
            float max_m = first ? -1e30f : 0.f;    // zeroed border contributes 0 for c>=1
#pragma unroll
            for (int j = 0; j < 6; j++) {
                int cnt = gg[j] - ((!first && j == jb) ? Nb : 0);
                float rv = dn[j] * w1;
                if (cnt > 0) { mean_m += (float)cnt * rv; max_m = fmaxf(max_m, rv); }
            }
            mean_m = __fdiv_rn(mean_m, Nf);
            if (max_m > 0.f) {
                float w2 = max_m - mean_m; w2 *= w2;   // min_m == 0 always
#pragma unroll
                for (int j = 0; j < 6; j++)
                    lut[j] = __fmul_rn(__fdiv_rn(dn[j] * w1, max_m), w2);
            }
        }
#pragma unroll
        for (int j = 0; j < 6; j++) g_lut[ch][j] = lut[j];
        s5part += lut[5];
        if (c == 0) sbord = lut[jb];
    }
    sh[threadIdx.x] = s5part;
    __syncthreads();
    for (int st = THREADS / 2; st; st >>= 1) {
        if (threadIdx.x < st) sh[threadIdx.x] += sh[threadIdx.x + st];
        __syncthreads();
    }
    if (threadIdx.x == 0) { g_S5[blockIdx.x] = sh[0]; g_bord[blockIdx.x] = sbord; }
}

// ---------------- pass scatter: apply rare corrections into zeroed g_proc ----------------
__global__ void __launch_bounds__(THREADS) k_scatter() {
    unsigned n = g_rarecnt;
    for (unsigned i = blockIdx.x * THREADS + threadIdx.x; i < n; i += gridDim.x * THREADS) {
        unsigned e = g_rare[i];
        unsigned pix = e & 0x3FFFFu;
        unsigned ch  = (e >> 18) & 0x7FFu;
        unsigned b2  = e >> 29;
        int layer = ch < 64 ? 0 : ch < 192 ? 1 : ch < 448 ? 2 : ch < 960 ? 3 : 4;
        float d = g_lut[ch][b2] - g_lut[ch][5];
        atomicAdd(&g_proc[c_procBase[layer] + pix], d);
    }
}

// ---------------- pass pstat: add base, write true proc, per-layer min/max ----------------
__global__ void __launch_bounds__(THREADS) k_pstat() {
    __shared__ float sred[16];
    int b = blockIdx.x;
    int layer, loc;
    if (b < 900)       { layer = 0; loc = b; }
    else if (b < 1125) { layer = 1; loc = b - 900; }
    else if (b < 1182) { layer = 2; loc = b - 1125; }
    else if (b < 1197) { layer = 3; loc = b - 1182; }
    else               { layer = 4; loc = b - 1197; }
    int W = c_H[layer], HW = W * W, pb = c_procBase[layer];
    int p = loc * THREADS + threadIdx.x;
    float vmn = 1e30f, vmx = -1e30f;
    if (p < HW) {
        int r = p / W, c = p - r * W;
        bool bd = (r == 0) | (c == 0) | (r == W - 1) | (c == W - 1);
        float base = bd ? g_bord[layer] : g_S5[layer];
        float val = base + g_proc[pb + p];
        g_proc[pb + p] = val;
        vmn = val; vmx = val;
    }
    blockMinMax(vmn, vmx, g_pstat[layer], sred);
}

// ---------------- pass E: normalize+threshold (fused) + resize + group min/max ----
__device__ __forceinline__ float fth(float v, float mnp, float rng) {
    float pn = (rng == 0.f) ? 0.f : __fdiv_rn(v - mnp, rng);
    return (pn < 0.2f) ? 0.f : pn;
}

__global__ void __launch_bounds__(THREADS) k_resize() {
    __shared__ float sred[16];
    int b = blockIdx.x;
    int layer = b / 225;
    int p = (b - layer * 225) * THREADS + threadIdx.x;   // < 57600 exactly
    int y = p / 240, x = p % 240;
    float mnp = fdec(g_pstat[layer][0]);
    float mxp = fdec(g_pstat[layer][1]);
    float rng = mxp - mnp;
    float val;
    if (layer == 0) {
        // 480 -> 240 antialiased: taps [1,3,3,1]/8, edge-renormalized
        const float w4[4] = {1.f, 3.f, 3.f, 1.f};
        float wxs = 0.f;
#pragma unroll
        for (int j = 0; j < 4; j++) { int tx = 2 * x - 1 + j; if (tx >= 0 && tx < 480) wxs += w4[j]; }
        float acc = 0.f, wys = 0.f;
#pragma unroll
        for (int a = 0; a < 4; a++) {
            int ty = 2 * y - 1 + a;
            if (ty < 0 || ty > 479) continue;
            wys += w4[a];
            const float* row = g_proc + ty * 480;
            float ra = 0.f;
#pragma unroll
            for (int j = 0; j < 4; j++) {
                int tx = 2 * x - 1 + j;
                if (tx >= 0 && tx < 480) ra += w4[j] * fth(row[tx], mnp, rng);
            }
            acc += w4[a] * ra;
        }
        val = acc / (wys * wxs);
    } else if (layer == 1) {
        val = fth(g_proc[230400 + p], mnp, rng);         // identity resize
    } else {
        int H = layer == 2 ? 120 : layer == 3 ? 60 : 30;
        int base = layer == 2 ? 288000 : layer == 3 ? 302400 : 306000;
        const float* pr = g_proc + base;
        float s = (float)H / 240.f;                      // 0.5 / 0.25 / 0.125 exact
        float cy = (y + 0.5f) * s - 0.5f;
        float cx = (x + 0.5f) * s - 0.5f;
        float fly = floorf(cy), flx = floorf(cx);
        float fy = cy - fly, fx = cx - flx;
        int iy = (int)fly, ix = (int)flx;
        int y0 = max(iy, 0), y1 = min(iy + 1, H - 1);
        int x0 = max(ix, 0), x1 = min(ix + 1, H - 1);
        float a = fth(pr[y0 * H + x0], mnp, rng), bv = fth(pr[y0 * H + x1], mnp, rng);
        float c = fth(pr[y1 * H + x0], mnp, rng), d = fth(pr[y1 * H + x1], mnp, rng);
        val = (1.f - fy) * ((1.f - fx) * a + fx * bv) + fy * ((1.f - fx) * c + fx * d);
    }
    g_group[layer][p] = val;
    blockMinMax(val, val, g_gstat[layer], sred);
}

// ---------------- pass F: group normalize(0,256), write groups + sum ----------------
__global__ void __launch_bounds__(THREADS) k_final(float* __restrict__ out, int out_size) {
    int p = blockIdx.x * THREADS + threadIdx.x;          // 225 blocks * 256 = 57600 exactly
    float s = 0.f;
#pragma unroll
    for (int g = 0; g < 5; g++) {
        float mn = fdec(g_gstat[g][0]);
        float mx = fdec(g_gstat[g][1]);
        float rng = mx - mn;
        float v = g_group[g][p];
        float gv = (rng == 0.f) ? 0.f : __fmul_rn(__fdiv_rn(v - mn, rng), 256.f);
        if (out_size >= 345600) out[57600 + p * 5 + g] = gv;
        s += gv;
    }
    out[p] = s;
}

// ---------------- launch ----------------
extern "C" void kernel_launch(void* const* d_in, const int* in_sizes, int n_in,
                              void* d_out, int out_size) {
    const int want[5] = {14745600, 7372800, 3686400, 1843200, 460800};
    const float* L[5] = {nullptr, nullptr, nullptr, nullptr, nullptr};
    for (int i = 0; i < n_in && i < 16; i++)
        for (int j = 0; j < 5; j++)
            if (in_sizes[i] == want[j] && L[j] == nullptr) { L[j] = (const float*)d_in[i]; break; }
    for (int j = 0; j < 5; j++) if (!L[j] && j < n_in) L[j] = (const float*)d_in[j];

    k_init<<<1199, THREADS>>>();
    k_maxhist<<<2304, THREADS>>>(L[0], L[1], L[2], L[3], L[4]);
    k_lut_s5<<<5, THREADS>>>();
    k_scatter<<<128, THREADS>>>();
    k_pstat<<<1201, THREADS>>>();
    k_resize<<<1125, THREADS>>>();
    k_final<<<225, THREADS>>>((float*)d_out, out_size);
}

// round 15
// speedup vs baseline: 1.2687x; 1.2687x over previous
#include <cuda_runtime.h>
#include <math.h>
#include <stdint.h>

#define THREADS 256
#define FULLM 0xFFFFFFFFu

// ---------------- layer tables ----------------
__constant__ int c_H[5]        = {480, 240, 120, 60, 30};
__constant__ int c_chanBase[5] = {0, 64, 192, 448, 960};
__constant__ int c_C[5]        = {64, 128, 256, 512, 512};
__constant__ int c_procBase[5] = {0, 230400, 288000, 302400, 306000};

// ---------------- scratch (device globals; no allocation) ----------------
__device__ unsigned g_cmax[1472];        // raw bits of per-channel max (values >= 0)
__device__ unsigned g_cnt[1472];         // tiles-arrived counter per channel
__device__ int      g_hist[1472][12];    // [0:6) histc bins, [6:12) gidx bins
__device__ float    g_lut[1472][6];      // per-channel contribution LUT
__device__ float    g_S5[5];             // sum_c lut_c[5] per layer
__device__ float    g_bord[5];           // border proc value per layer
__device__ unsigned g_rarecnt;
__device__ unsigned g_rare[28108800];    // packed rare records: pix|ch<<18|b2<<29
__device__ float    g_proc[306900];      // corrections (zeroed), then full proc values
__device__ unsigned g_pstat[5][2];       // proc min/max per layer (encoded)
__device__ float    g_group[5][57600];   // resized+thresholded maps
__device__ unsigned g_gstat[5][2];       // group min/max per layer (encoded)

// ---------------- float <-> orderable uint ----------------
__device__ __forceinline__ unsigned fenc(float f) {
    unsigned b = __float_as_uint(f);
    return (b & 0x80000000u) ? ~b : (b | 0x80000000u);
}
__device__ __forceinline__ float fdec(unsigned u) {
    unsigned b = (u & 0x80000000u) ? (u & 0x7FFFFFFFu) : ~u;
    return __uint_as_float(b);
}

__device__ __forceinline__ void blockMinMax(float vmn, float vmx, unsigned* stat, float* s) {
#pragma unroll
    for (int o = 16; o; o >>= 1) {
        vmn = fminf(vmn, __shfl_xor_sync(FULLM, vmn, o));
        vmx = fmaxf(vmx, __shfl_xor_sync(FULLM, vmx, o));
    }
    int w = threadIdx.x >> 5;
    if ((threadIdx.x & 31) == 0) { s[w] = vmn; s[8 + w] = vmx; }
    __syncthreads();
    if (threadIdx.x == 0) {
        float a = s[0], b = s[8];
#pragma unroll
        for (int i = 1; i < 8; i++) { a = fminf(a, s[i]); b = fmaxf(b, s[8 + i]); }
        atomicMin(&stat[0], fenc(a));
        atomicMax(&stat[1], fenc(b));
    }
    __syncthreads();
}

// ---------------- pass 0: init ----------------
__global__ void __launch_bounds__(THREADS) k_init() {
    int i = blockIdx.x * THREADS + threadIdx.x;
    if (i < 306900) g_proc[i] = 0.f;          // correction buffer starts zeroed
    if (i < 1472 * 12) ((int*)g_hist)[i] = 0;
    if (i < 1472) { g_cmax[i] = 0u; g_cnt[i] = 0u; }
    if (i == 0) g_rarecnt = 0u;
    if (i < 5) {
        g_pstat[i][0] = 0xFFFFFFFFu; g_pstat[i][1] = 0u;
        g_gstat[i][0] = 0xFFFFFFFFu; g_gstat[i][1] = 0u;
    }
}

// ---------------- fused max+hist (R10 structure, unchanged) ----------------
// tiles per channel: {32,8,2,1,1}; blocks per layer {2048,1024,512,512,512}; total 4608

__device__ __forceinline__ void hist_flush1(unsigned long long h1, int ch) {
#pragma unroll
    for (int j = 0; j < 6; j++) {
        int c1 = (int)((h1 >> (j * 10)) & 1023u);
        c1 = __reduce_add_sync(FULLM, c1);
        if ((threadIdx.x & 31) == 0 && c1) atomicAdd(&g_hist[ch][j], c1);
    }
}

__device__ __forceinline__ void emit4(unsigned msk, const unsigned* rec, const int* b2, int ch) {
    unsigned any = __ballot_sync(FULLM, msk != 0);
    if (!any) return;
    unsigned lane = threadIdx.x & 31;
    int cnt = __popc(msk);
    int pre = cnt;
#pragma unroll
    for (int o = 1; o < 32; o <<= 1) {
        int t = __shfl_up_sync(FULLM, pre, o);
        if (lane >= o) pre += t;
    }
    int tot = __shfl_sync(FULLM, pre, 31);
    unsigned bs = 0;
    if (lane == 31) bs = atomicAdd(&g_rarecnt, (unsigned)tot);
    bs = __shfl_sync(FULLM, bs, 31);
    unsigned off = bs + (unsigned)(pre - cnt);
#pragma unroll
    for (int k = 0; k < 4; k++) {
        if ((msk >> k) & 1u) {
            g_rare[off++] = rec[k];
            atomicAdd(&g_hist[ch][6 + b2[k]], 1);
        }
    }
}

template <int NT>
__device__ __forceinline__ float sync_chmax(float mx, int ch, float* sred, float* smx) {
#pragma unroll
    for (int o = 16; o; o >>= 1) mx = fmaxf(mx, __shfl_xor_sync(FULLM, mx, o));
    if ((threadIdx.x & 31) == 0) sred[threadIdx.x >> 5] = mx;
    __syncthreads();
    if (threadIdx.x == 0) {
        float a = sred[0];
#pragma unroll
        for (int i = 1; i < 8; i++) a = fmaxf(a, sred[i]);
        atomicMax(&g_cmax[ch], __float_as_uint(a));   // nonneg floats: raw-bit monotonic
        if (NT > 1) {
            __threadfence();
            atomicAdd(&g_cnt[ch], 1u);
            while (*(volatile unsigned*)&g_cnt[ch] < (unsigned)NT) __nanosleep(64);
            __threadfence();
        }
        *smx = __uint_as_float(*(volatile unsigned*)&g_cmax[ch]);
    }
    __syncthreads();
    return *smx;
}

template <int H, int T, int NT>
__device__ void fused_v(const float* __restrict__ base, int tile, int ch,
                        float* sred, float* smx) {
    constexpr int W = H, F4 = W / 4;
    int rowsThis = (H - 2 - tile + T - 1) / T;
    int total = rowsThis * F4;
    float mx = 0.f;
#pragma unroll 4
    for (int i = threadIdx.x; i < total; i += THREADS) {
        int m = i / F4, j = i - m * F4;
        int r = 1 + tile + m * T;
        float4 v = *(const float4*)(base + r * W + 4 * j);
        if (j == 0) v.x = 0.f;
        if (j == F4 - 1) v.w = 0.f;
        mx = fmaxf(mx, fmaxf(fmaxf(v.x, v.y), fmaxf(v.z, v.w)));
    }
    float mxc = sync_chmax<NT>(mx, ch, sred, smx);
    float s = (mxc > 0.f) ? __fdiv_rn(1536.f, mxc) : 0.f;
    unsigned long long h1 = 0ULL;
    int iters = (total + THREADS - 1) / THREADS;
    for (int it = 0; it < iters; it++) {
        int i = it * THREADS + threadIdx.x;
        bool ok = i < total;
        int ii = ok ? i : 0;
        int m = ii / F4, j = ii - m * F4;
        int r = 1 + tile + m * T;
        float4 v = ok ? *(const float4*)(base + r * W + 4 * j)
                      : make_float4(1e30f, 1e30f, 1e30f, 1e30f);
        if (ok) {
            if (j == 0) v.x = 0.f;
            if (j == F4 - 1) v.w = 0.f;
        }
        int i1[4];
        i1[0] = __float2int_rd(__fmul_rn(v.x, s));
        i1[1] = __float2int_rd(__fmul_rn(v.y, s));
        i1[2] = __float2int_rd(__fmul_rn(v.z, s));
        i1[3] = __float2int_rd(__fmul_rn(v.w, s));
        if (ok) {
#pragma unroll
            for (int k = 0; k < 4; k++) h1 += 1ULL << (min(i1[k] >> 8, 5) * 10);
        }
        unsigned pix = (unsigned)(r * W + 4 * j);
        unsigned msk = 0;
        unsigned rec[4]; int b2a[4];
        if (ok) {
#pragma unroll
            for (int k = 0; k < 4; k++) {
                bool rr = (i1[k] < 6);
                if (k == 0) rr = rr && (j != 0);          // border col 0: analytic
                if (k == 3) rr = rr && (j != F4 - 1);     // border col W-1: analytic
                int b2 = max(i1[k] - 1, 0);
                b2a[k] = b2;
                rec[k] = (pix + k) | ((unsigned)ch << 18) | ((unsigned)b2 << 29);
                if (rr) msk |= 1u << k;
            }
        }
        emit4(msk, rec, b2a, ch);
    }
    hist_flush1(h1, ch);
    if (tile == 0 && threadIdx.x == 0) {
        atomicAdd(&g_hist[ch][0], 2 * W);                 // rows 0,H-1 -> histc bin 0
        atomicAdd(&g_hist[ch][6 + 0], 2 * (H + W) - 4);   // full border -> gidx bin 0
    }
}

template <int H>
__device__ void fused_s(const float* __restrict__ base, int ch, float* sred, float* smx) {
    constexpr int W = H, IW = W - 2, NI = IW * (H - 2);
    float mx = 0.f;
    for (int i = threadIdx.x; i < NI; i += THREADS) {
        int q = i / IW, col = i - q * IW;
        mx = fmaxf(mx, base[(q + 1) * W + col + 1]);
    }
    float mxc = sync_chmax<1>(mx, ch, sred, smx);
    float s = (mxc > 0.f) ? __fdiv_rn(1536.f, mxc) : 0.f;
    unsigned long long h1 = 0ULL;
    int iters = (NI + THREADS - 1) / THREADS;
    for (int it = 0; it < iters; it++) {
        int i = it * THREADS + threadIdx.x;
        bool ok = i < NI;
        int ii = ok ? i : 0;
        int q = ii / IW, col = ii - q * IW;
        int pix = (q + 1) * W + col + 1;
        float v = ok ? base[pix] : 1e30f;
        int i1 = __float2int_rd(__fmul_rn(v, s));
        if (ok) h1 += 1ULL << (min(i1 >> 8, 5) * 10);
        unsigned msk = (ok && i1 < 6) ? 1u : 0u;
        int b2 = max(i1 - 1, 0);
        unsigned rec[4]; int b2a[4];
        rec[0] = (unsigned)pix | ((unsigned)ch << 18) | ((unsigned)b2 << 29);
        b2a[0] = b2;
        rec[1] = rec[2] = rec[3] = 0; b2a[1] = b2a[2] = b2a[3] = 0;
        emit4(msk, rec, b2a, ch);
    }
    hist_flush1(h1, ch);
    if (threadIdx.x == 0) {
        int Nb = 2 * (H + W) - 4;
        atomicAdd(&g_hist[ch][0], Nb);
        atomicAdd(&g_hist[ch][6 + 0], Nb);
    }
}

__global__ void __launch_bounds__(THREADS) k_maxhist(const float* __restrict__ p0, const float* __restrict__ p1,
                                                     const float* __restrict__ p2, const float* __restrict__ p3,
                                                     const float* __restrict__ p4) {
    __shared__ float sred[8];
    __shared__ float smx;
    int b = blockIdx.x;
    if (b < 2048) {
        int cloc = b >> 5, tile = b & 31;
        fused_v<480, 32, 32>(p0 + (long long)cloc * 230400, tile, cloc, sred, &smx);
    } else if (b < 3072) {
        int t = b - 2048, cloc = t >> 3, tile = t & 7;
        fused_v<240, 8, 8>(p1 + (long long)cloc * 57600, tile, 64 + cloc, sred, &smx);
    } else if (b < 3584) {
        int t = b - 3072, cloc = t >> 1, tile = t & 1;
        fused_v<120, 2, 2>(p2 + (long long)cloc * 14400, tile, 192 + cloc, sred, &smx);
    } else if (b < 4096) {
        int cloc = b - 3584;
        fused_v<60, 1, 1>(p3 + (long long)cloc * 3600, 0, 448 + cloc, sred, &smx);
    } else {
        int cloc = b - 4096;
        fused_s<30>(p4 + (long long)cloc * 900, 960 + cloc, sred, &smx);
    }
}

// ---------------- pass LUT+S5: per-channel LUT, then per-layer S5/bord ----------------
__global__ void __launch_bounds__(THREADS) k_lut_s5() {
    __shared__ float sh[THREADS];
    __shared__ float sbord;
    int l = blockIdx.x;
    int C = c_C[l], cb = c_chanBase[l];
    int H = c_H[l], W = H, HW = H * W;
    float Nf = (float)HW;
    float s5part = 0.f;
    for (int c = threadIdx.x; c < C; c += THREADS) {
        int ch = cb + c;
        int gg[6], sg = 0;
#pragma unroll
        for (int j = 0; j < 5; j++) { gg[j] = g_hist[ch][6 + j]; sg += gg[j]; }
        gg[5] = HW - sg;                      // all non-rare interior pixels have gidx 5

        float hv[6];
#pragma unroll
        for (int j = 0; j < 6; j++)
            hv[j] = -logf(__fdiv_rn((float)g_hist[ch][j], Nf) + 1e-4f);

        float minv = 1e30f, maxv = -1e30f;
#pragma unroll
        for (int j = 0; j < 6; j++)
            if (gg[j] > 0) { minv = fminf(minv, hv[j]); maxv = fmaxf(maxv, hv[j]); }
        float rh = maxv - minv;

        const int jb = 0;                      // border pixels (value 0) -> gidx bin 0
        bool first = (c == 0);                 // channel 0 keeps its border in the map

        float lut[6] = {0.f, 0.f, 0.f, 0.f, 0.f, 0.f};
        if (rh > 0.f) {
            float dn[6];
#pragma unroll
            for (int j = 0; j < 6; j++)
                dn[j] = (gg[j] > 0) ? __fdiv_rn(hv[j] - minv, rh) : 0.f;
            float meandn = 0.f;
#pragma unroll
            for (int j = 0; j < 6; j++) meandn += (float)gg[j] * dn[j];
            meandn = __fdiv_rn(meandn, Nf);
            float w1 = 1.f - meandn; w1 *= w1;     // (max_dst - mean_dst)^2
            int Nb = 2 * (H + W) - 4;
            float mean_m = 0.f;
            float max_m = first ? -1e30f : 0.f;    // zeroed border contributes 0 for c>=1
#pragma unroll
            for (int j = 0; j < 6; j++) {
                int cnt = gg[j] - ((!first && j == jb) ? Nb : 0);
                float rv = dn[j] * w1;
                if (cnt > 0) { mean_m += (float)cnt * rv; max_m = fmaxf(max_m, rv); }
            }
            mean_m = __fdiv_rn(mean_m, Nf);
            if (max_m > 0.f) {
                float w2 = max_m - mean_m; w2 *= w2;   // min_m == 0 always
#pragma unroll
                for (int j = 0; j < 6; j++)
                    lut[j] = __fmul_rn(__fdiv_rn(dn[j] * w1, max_m), w2);
            }
        }
#pragma unroll
        for (int j = 0; j < 6; j++) g_lut[ch][j] = lut[j];
        s5part += lut[5];
        if (c == 0) sbord = lut[jb];
    }
    sh[threadIdx.x] = s5part;
    __syncthreads();
    for (int st = THREADS / 2; st; st >>= 1) {
        if (threadIdx.x < st) sh[threadIdx.x] += sh[threadIdx.x + st];
        __syncthreads();
    }
    if (threadIdx.x == 0) { g_S5[blockIdx.x] = sh[0]; g_bord[blockIdx.x] = sbord; }
}

// ---------------- pass scatter: apply rare corrections into zeroed g_proc ----------------
__global__ void __launch_bounds__(THREADS) k_scatter() {
    unsigned n = g_rarecnt;
    for (unsigned i = blockIdx.x * THREADS + threadIdx.x; i < n; i += gridDim.x * THREADS) {
        unsigned e = g_rare[i];
        unsigned pix = e & 0x3FFFFu;
        unsigned ch  = (e >> 18) & 0x7FFu;
        unsigned b2  = e >> 29;
        int layer = ch < 64 ? 0 : ch < 192 ? 1 : ch < 448 ? 2 : ch < 960 ? 3 : 4;
        float d = g_lut[ch][b2] - g_lut[ch][5];
        atomicAdd(&g_proc[c_procBase[layer] + pix], d);
    }
}

// ---------------- pass pstat: add base (S5/bord), write true proc, min/max ----------------
__global__ void __launch_bounds__(THREADS) k_pstat() {
    __shared__ float sred[16];
    int b = blockIdx.x;
    int layer, loc;
    if (b < 900)       { layer = 0; loc = b; }
    else if (b < 1125) { layer = 1; loc = b - 900; }
    else if (b < 1182) { layer = 2; loc = b - 1125; }
    else if (b < 1197) { layer = 3; loc = b - 1182; }
    else               { layer = 4; loc = b - 1197; }
    int W = c_H[layer], HW = W * W, pb = c_procBase[layer];
    int p = loc * THREADS + threadIdx.x;
    float vmn = 1e30f, vmx = -1e30f;
    if (p < HW) {
        int r = p / W, c = p - r * W;
        bool bd = (r == 0) | (c == 0) | (r == W - 1) | (c == W - 1);
        float base = bd ? g_bord[layer] : g_S5[layer];
        float val = base + g_proc[pb + p];
        g_proc[pb + p] = val;
        vmn = val; vmx = val;
    }
    blockMinMax(vmn, vmx, g_pstat[layer], sred);
}

// ---------------- pass E: normalize+threshold (fused) + resize + group min/max ----
__device__ __forceinline__ float fth(float v, float mnp, float rng) {
    float pn = (rng == 0.f) ? 0.f : __fdiv_rn(v - mnp, rng);
    return (pn < 0.2f) ? 0.f : pn;
}

__global__ void __launch_bounds__(THREADS) k_resize() {
    __shared__ float sred[16];
    int b = blockIdx.x;
    int layer = b / 225;
    int p = (b - layer * 225) * THREADS + threadIdx.x;   // < 57600 exactly
    int y = p / 240, x = p % 240;
    float mnp = fdec(g_pstat[layer][0]);
    float mxp = fdec(g_pstat[layer][1]);
    float rng = mxp - mnp;
    float val;
    if (layer == 0) {
        // 480 -> 240 antialiased: taps [1,3,3,1]/8, edge-renormalized
        const float w4[4] = {1.f, 3.f, 3.f, 1.f};
        float wxs = 0.f;
#pragma unroll
        for (int j = 0; j < 4; j++) { int tx = 2 * x - 1 + j; if (tx >= 0 && tx < 480) wxs += w4[j]; }
        float acc = 0.f, wys = 0.f;
#pragma unroll
        for (int a = 0; a < 4; a++) {
            int ty = 2 * y - 1 + a;
            if (ty < 0 || ty > 479) continue;
            wys += w4[a];
            const float* row = g_proc + ty * 480;
            float ra = 0.f;
#pragma unroll
            for (int j = 0; j < 4; j++) {
                int tx = 2 * x - 1 + j;
                if (tx >= 0 && tx < 480) ra += w4[j] * fth(row[tx], mnp, rng);
            }
            acc += w4[a] * ra;
        }
        val = acc / (wys * wxs);
    } else if (layer == 1) {
        val = fth(g_proc[230400 + p], mnp, rng);         // identity resize
    } else {
        int H = layer == 2 ? 120 : layer == 3 ? 60 : 30;
        int base = layer == 2 ? 288000 : layer == 3 ? 302400 : 306000;
        const float* pr = g_proc + base;
        float s = (float)H / 240.f;                      // 0.5 / 0.25 / 0.125 exact
        float cy = (y + 0.5f) * s - 0.5f;
        float cx = (x + 0.5f) * s - 0.5f;
        float fly = floorf(cy), flx = floorf(cx);
        float fy = cy - fly, fx = cx - flx;
        int iy = (int)fly, ix = (int)flx;
        int y0 = max(iy, 0), y1 = min(iy + 1, H - 1);
        int x0 = max(ix, 0), x1 = min(ix + 1, H - 1);
        float a = fth(pr[y0 * H + x0], mnp, rng), bv = fth(pr[y0 * H + x1], mnp, rng);
        float c = fth(pr[y1 * H + x0], mnp, rng), d = fth(pr[y1 * H + x1], mnp, rng);
        val = (1.f - fy) * ((1.f - fx) * a + fx * bv) + fy * ((1.f - fx) * c + fx * d);
    }
    g_group[layer][p] = val;
    blockMinMax(val, val, g_gstat[layer], sred);
}

// ---------------- pass F: group normalize(0,256), write groups + sum ----------------
__global__ void __launch_bounds__(THREADS) k_final(float* __restrict__ out, int out_size) {
    int p = blockIdx.x * THREADS + threadIdx.x;          // 225 blocks * 256 = 57600 exactly
    float s = 0.f;
#pragma unroll
    for (int g = 0; g < 5; g++) {
        float mn = fdec(g_gstat[g][0]);
        float mx = fdec(g_gstat[g][1]);
        float rng = mx - mn;
        float v = g_group[g][p];
        float gv = (rng == 0.f) ? 0.f : __fmul_rn(__fdiv_rn(v - mn, rng), 256.f);
        if (out_size >= 345600) out[57600 + p * 5 + g] = gv;
        s += gv;
    }
    out[p] = s;
}

// ---------------- launch ----------------
extern "C" void kernel_launch(void* const* d_in, const int* in_sizes, int n_in,
                              void* d_out, int out_size) {
    const int want[5] = {14745600, 7372800, 3686400, 1843200, 460800};
    const float* L[5] = {nullptr, nullptr, nullptr, nullptr, nullptr};
    for (int i = 0; i < n_in && i < 16; i++)
        for (int j = 0; j < 5; j++)
            if (in_sizes[i] == want[j] && L[j] == nullptr) { L[j] = (const float*)d_in[i]; break; }
    for (int j = 0; j < 5; j++) if (!L[j] && j < n_in) L[j] = (const float*)d_in[j];

    k_init<<<1199, THREADS>>>();
    k_maxhist<<<4608, THREADS>>>(L[0], L[1], L[2], L[3], L[4]);
    k_lut_s5<<<5, THREADS>>>();
    k_scatter<<<592, THREADS>>>();
    k_pstat<<<1201, THREADS>>>();
    k_resize<<<1125, THREADS>>>();
    k_final<<<225, THREADS>>>((float*)d_out, out_size);
}

// round 16
// speedup vs baseline: 1.3579x; 1.0703x over previous
#include <cuda_runtime.h>
#include <math.h>
#include <stdint.h>

#define THREADS 256
#define FULLM 0xFFFFFFFFu
#define DEFCAP 2048

// ---------------- layer tables ----------------
__constant__ int c_H[5]        = {480, 240, 120, 60, 30};
__constant__ int c_chanBase[5] = {0, 64, 192, 448, 960};
__constant__ int c_C[5]        = {64, 128, 256, 512, 512};
__constant__ int c_procBase[5] = {0, 230400, 288000, 302400, 306000};

// ---------------- scratch (device globals; no allocation) ----------------
__device__ unsigned g_cmax[1472];        // raw bits of per-channel max (values >= 0)
__device__ unsigned g_cnt[1472];         // tiles-arrived counter per channel
__device__ int      g_hist[1472][12];    // [0:6) histc bins, [6:12) gidx bins
__device__ float    g_lut[1472][6];      // per-channel contribution LUT
__device__ float    g_S5[5];             // sum_c lut_c[5] per layer
__device__ float    g_bord[5];           // border proc value per layer
__device__ unsigned g_rarecnt;
__device__ unsigned g_rare[28108800];    // packed rare records: pix|ch<<18|b2<<29
__device__ float    g_proc[306900];      // corrections (zeroed), then full proc values
__device__ unsigned g_pstat[5][2];       // proc min/max per layer (encoded)
__device__ float    g_group[5][57600];   // resized+thresholded maps
__device__ unsigned g_gstat[5][2];       // group min/max per layer (encoded)

// ---------------- float <-> orderable uint ----------------
__device__ __forceinline__ unsigned fenc(float f) {
    unsigned b = __float_as_uint(f);
    return (b & 0x80000000u) ? ~b : (b | 0x80000000u);
}
__device__ __forceinline__ float fdec(unsigned u) {
    unsigned b = (u & 0x80000000u) ? (u & 0x7FFFFFFFu) : ~u;
    return __uint_as_float(b);
}

__device__ __forceinline__ void blockMinMax(float vmn, float vmx, unsigned* stat, float* s) {
#pragma unroll
    for (int o = 16; o; o >>= 1) {
        vmn = fminf(vmn, __shfl_xor_sync(FULLM, vmn, o));
        vmx = fmaxf(vmx, __shfl_xor_sync(FULLM, vmx, o));
    }
    int w = threadIdx.x >> 5;
    if ((threadIdx.x & 31) == 0) { s[w] = vmn; s[8 + w] = vmx; }
    __syncthreads();
    if (threadIdx.x == 0) {
        float a = s[0], b = s[8];
#pragma unroll
        for (int i = 1; i < 8; i++) { a = fminf(a, s[i]); b = fmaxf(b, s[8 + i]); }
        atomicMin(&stat[0], fenc(a));
        atomicMax(&stat[1], fenc(b));
    }
    __syncthreads();
}

// ---------------- pass 0: init ----------------
__global__ void __launch_bounds__(THREADS) k_init() {
    int i = blockIdx.x * THREADS + threadIdx.x;
    if (i < 306900) g_proc[i] = 0.f;          // correction buffer starts zeroed
    if (i < 1472 * 12) ((int*)g_hist)[i] = 0;
    if (i < 1472) { g_cmax[i] = 0u; g_cnt[i] = 0u; }
    if (i == 0) g_rarecnt = 0u;
    if (i < 5) {
        g_pstat[i][0] = 0xFFFFFFFFu; g_pstat[i][1] = 0u;
        g_gstat[i][0] = 0xFFFFFFFFu; g_gstat[i][1] = 0u;
    }
}

// ---------------- fused max+hist (single global sweep via q-cache) ----------------
// tiles per channel: {32,8,2,1,1}; blocks per layer {2048,1024,512,512,512}; total 4608

__device__ __forceinline__ void hist_flush1(unsigned long long h1, int ch) {
#pragma unroll
    for (int j = 0; j < 6; j++) {
        int c1 = (int)((h1 >> (j * 10)) & 1023u);
        c1 = __reduce_add_sync(FULLM, c1);
        if ((threadIdx.x & 31) == 0 && c1) atomicAdd(&g_hist[ch][j], c1);
    }
}

__device__ __forceinline__ void emit4(unsigned msk, const unsigned* rec, const int* b2, int ch) {
    unsigned any = __ballot_sync(FULLM, msk != 0);
    if (!any) return;
    unsigned lane = threadIdx.x & 31;
    int cnt = __popc(msk);
    int pre = cnt;
#pragma unroll
    for (int o = 1; o < 32; o <<= 1) {
        int t = __shfl_up_sync(FULLM, pre, o);
        if (lane >= o) pre += t;
    }
    int tot = __shfl_sync(FULLM, pre, 31);
    unsigned bs = 0;
    if (lane == 31) bs = atomicAdd(&g_rarecnt, (unsigned)tot);
    bs = __shfl_sync(FULLM, bs, 31);
    unsigned off = bs + (unsigned)(pre - cnt);
#pragma unroll
    for (int k = 0; k < 4; k++) {
        if ((msk >> k) & 1u) {
            g_rare[off++] = rec[k];
            atomicAdd(&g_hist[ch][6 + b2[k]], 1);
        }
    }
}

template <int NT>
__device__ __forceinline__ float sync_chmax(float mx, int ch, float* sred, float* smx) {
#pragma unroll
    for (int o = 16; o; o >>= 1) mx = fmaxf(mx, __shfl_xor_sync(FULLM, mx, o));
    if ((threadIdx.x & 31) == 0) sred[threadIdx.x >> 5] = mx;
    __syncthreads();
    if (threadIdx.x == 0) {
        float a = sred[0];
#pragma unroll
        for (int i = 1; i < 8; i++) a = fmaxf(a, sred[i]);
        atomicMax(&g_cmax[ch], __float_as_uint(a));   // nonneg floats: raw-bit monotonic
        if (NT > 1) {
            __threadfence();
            atomicAdd(&g_cnt[ch], 1u);
            while (*(volatile unsigned*)&g_cnt[ch] < (unsigned)NT) __nanosleep(64);
            __threadfence();
        }
        *smx = __uint_as_float(*(volatile unsigned*)&g_cmax[ch]);
    }
    __syncthreads();
    return *smx;
}

// drain deferred (ambiguous) pixels: batched global re-read, original exact formula
template <int H, int T>
__device__ void drain_def(const float* __restrict__ base, int tile, int ch, float s,
                          ushort* sdef, unsigned* scnt, unsigned long long& h1) {
    constexpr int W = H, F4 = W / 4;
    unsigned n = *scnt;
    for (unsigned b0 = 0; b0 < n; b0 += THREADS) {
        unsigned t = b0 + threadIdx.x;
        bool ok = t < n;
        int pxi = ok ? (int)sdef[t] : 0;
        int i4 = pxi >> 2, k = pxi & 3;
        int m = i4 / F4, j = i4 - m * F4;
        int r = 1 + tile + m * T;
        bool masked = (k == 0 && j == 0) || (k == 3 && j == F4 - 1);
        float v = (ok && !masked) ? base[r * W + 4 * j + k] : 0.f;
        int i1 = __float2int_rd(__fmul_rn(v, s));
        if (ok) h1 += 1ULL << (min(i1 >> 8, 5) * 10);
        bool rr = ok && !masked && (i1 < 6);
        int b2 = max(i1 - 1, 0);
        unsigned rec[4]; int b2a[4];
        rec[0] = (unsigned)(r * W + 4 * j + k) | ((unsigned)ch << 18) | ((unsigned)b2 << 29);
        b2a[0] = b2; rec[1] = rec[2] = rec[3] = 0;
        b2a[1] = b2a[2] = b2a[3] = 0;
        emit4(rr ? 1u : 0u, rec, b2a, ch);
    }
    __syncthreads();
    if (threadIdx.x == 0) *scnt = 0;
    __syncthreads();
}

template <int H, int T, int NT>
__device__ void fused_q(const float* __restrict__ base, int tile, int ch,
                        ushort* sq, unsigned char* slut, ushort* sdef,
                        unsigned* scnt, float* sred, float* smx) {
    constexpr int W = H, F4 = W / 4;
    int rowsThis = (H - 2 - tile + T - 1) / T;
    int total = rowsThis * F4;
    // -------- phase 1: single global sweep; max + q-cache to smem --------
    float mx = 0.f;
#pragma unroll 4
    for (int i = threadIdx.x; i < total; i += THREADS) {
        int m = i / F4, j = i - m * F4;
        int r = 1 + tile + m * T;
        float4 v = *(const float4*)(base + r * W + 4 * j);
        if (j == 0) v.x = 0.f;
        if (j == F4 - 1) v.w = 0.f;
        mx = fmaxf(mx, fmaxf(fmaxf(v.x, v.y), fmaxf(v.z, v.w)));
        int q0 = min(max(__float2int_rd(__fmul_rn(v.x, 1536.f)), 0), 1535);
        int q1 = min(max(__float2int_rd(__fmul_rn(v.y, 1536.f)), 0), 1535);
        int q2 = min(max(__float2int_rd(__fmul_rn(v.z, 1536.f)), 0), 1535);
        int q3 = min(max(__float2int_rd(__fmul_rn(v.w, 1536.f)), 0), 1535);
        uint2 pk;
        pk.x = (unsigned)q0 | ((unsigned)q1 << 16);
        pk.y = (unsigned)q2 | ((unsigned)q3 << 16);
        *(uint2*)(sq + 4 * i) = pk;
    }
    if (threadIdx.x == 0) *scnt = 0;
    float mxc = sync_chmax<NT>(mx, ch, sred, smx);
    float s = (mxc > 0.f) ? __fdiv_rn(1536.f, mxc) : 0.f;
    // -------- build per-block q -> (b1 | defer) LUT --------
    {
        double md = (double)mxc;
        int Qb0 = (int)(256.0 * md), Qb1 = (int)(512.0 * md), Qb2 = (int)(768.0 * md);
        int Qb3 = (int)(1024.0 * md), Qb4 = (int)(1280.0 * md);
        for (int e = threadIdx.x; e < 1536; e += THREADS) {
            bool amb = (e <= 6) || e == Qb0 || e == Qb1 || e == Qb2 || e == Qb3 || e == Qb4;
            int b1 = (e > Qb0) + (e > Qb1) + (e > Qb2) + (e > Qb3) + (e > Qb4);
            slut[e] = amb ? 255 : (unsigned char)b1;
        }
    }
    __syncthreads();
    // -------- phase 2: classify from smem q; defer ambiguous --------
    unsigned long long h1 = 0ULL;
    int iters = (total + THREADS - 1) / THREADS;
    for (int it = 0; it < iters; it++) {
        int i = it * THREADS + threadIdx.x;
        bool ok = i < total;
        int ii = ok ? i : 0;
        uint2 pk = *(const uint2*)(sq + 4 * ii);
        int q[4] = { (int)(pk.x & 0xFFFFu), (int)(pk.x >> 16),
                     (int)(pk.y & 0xFFFFu), (int)(pk.y >> 16) };
        if (ok) {
#pragma unroll
            for (int k = 0; k < 4; k++) {
                unsigned c = slut[q[k]];
                if (c == 255u) {
                    unsigned slot = atomicAdd(scnt, 1u);
                    sdef[slot] = (ushort)(4 * ii + k);   // slot < DEFCAP by drain policy
                } else {
                    h1 += 1ULL << (c * 10);
                }
            }
        }
        __syncthreads();
        if (*scnt >= (unsigned)(DEFCAP - 4 * THREADS))
            drain_def<H, T>(base, tile, ch, s, sdef, scnt, h1);
    }
    drain_def<H, T>(base, tile, ch, s, sdef, scnt, h1);
    hist_flush1(h1, ch);
    if (tile == 0 && threadIdx.x == 0) {
        atomicAdd(&g_hist[ch][0], 2 * W);                 // rows 0,H-1 -> histc bin 0
        atomicAdd(&g_hist[ch][6 + 0], 2 * (H + W) - 4);   // full border -> gidx bin 0
    }
}

// scalar two-sweep variant (layer 4, W=30; 0.5% of data)
template <int H>
__device__ void fused_s(const float* __restrict__ base, int ch, float* sred, float* smx) {
    constexpr int W = H, IW = W - 2, NI = IW * (H - 2);
    float mx = 0.f;
    for (int i = threadIdx.x; i < NI; i += THREADS) {
        int q = i / IW, col = i - q * IW;
        mx = fmaxf(mx, base[(q + 1) * W + col + 1]);
    }
    float mxc = sync_chmax<1>(mx, ch, sred, smx);
    float s = (mxc > 0.f) ? __fdiv_rn(1536.f, mxc) : 0.f;
    unsigned long long h1 = 0ULL;
    int iters = (NI + THREADS - 1) / THREADS;
    for (int it = 0; it < iters; it++) {
        int i = it * THREADS + threadIdx.x;
        bool ok = i < NI;
        int ii = ok ? i : 0;
        int q = ii / IW, col = ii - q * IW;
        int pix = (q + 1) * W + col + 1;
        float v = ok ? base[pix] : 1e30f;
        int i1 = __float2int_rd(__fmul_rn(v, s));
        if (ok) h1 += 1ULL << (min(i1 >> 8, 5) * 10);
        unsigned msk = (ok && i1 < 6) ? 1u : 0u;
        int b2 = max(i1 - 1, 0);
        unsigned rec[4]; int b2a[4];
        rec[0] = (unsigned)pix | ((unsigned)ch << 18) | ((unsigned)b2 << 29);
        b2a[0] = b2;
        rec[1] = rec[2] = rec[3] = 0; b2a[1] = b2a[2] = b2a[3] = 0;
        emit4(msk, rec, b2a, ch);
    }
    hist_flush1(h1, ch);
    if (threadIdx.x == 0) {
        int Nb = 2 * (H + W) - 4;
        atomicAdd(&g_hist[ch][0], Nb);
        atomicAdd(&g_hist[ch][6 + 0], Nb);
    }
}

__global__ void __launch_bounds__(THREADS) k_maxhist(const float* __restrict__ p0, const float* __restrict__ p1,
                                                     const float* __restrict__ p2, const float* __restrict__ p3,
                                                     const float* __restrict__ p4) {
    __shared__ ushort sq[7232];
    __shared__ unsigned char slut[1536];
    __shared__ ushort sdef[DEFCAP];
    __shared__ float sred[8];
    __shared__ float smx;
    __shared__ unsigned scnt;
    int b = blockIdx.x;
    if (b < 2048) {
        int cloc = b >> 5, tile = b & 31;
        fused_q<480, 32, 32>(p0 + (long long)cloc * 230400, tile, cloc, sq, slut, sdef, &scnt, sred, &smx);
    } else if (b < 3072) {
        int t = b - 2048, cloc = t >> 3, tile = t & 7;
        fused_q<240, 8, 8>(p1 + (long long)cloc * 57600, tile, 64 + cloc, sq, slut, sdef, &scnt, sred, &smx);
    } else if (b < 3584) {
        int t = b - 3072, cloc = t >> 1, tile = t & 1;
        fused_q<120, 2, 2>(p2 + (long long)cloc * 14400, tile, 192 + cloc, sq, slut, sdef, &scnt, sred, &smx);
    } else if (b < 4096) {
        int cloc = b - 3584;
        fused_q<60, 1, 1>(p3 + (long long)cloc * 3600, 0, 448 + cloc, sq, slut, sdef, &scnt, sred, &smx);
    } else {
        int cloc = b - 4096;
        fused_s<30>(p4 + (long long)cloc * 900, 960 + cloc, sred, &smx);
    }
}

// ---------------- pass LUT+S5: per-channel LUT, then per-layer S5/bord ----------------
__global__ void __launch_bounds__(THREADS) k_lut_s5() {
    __shared__ float sh[THREADS];
    __shared__ float sbord;
    int l = blockIdx.x;
    int C = c_C[l], cb = c_chanBase[l];
    int H = c_H[l], W = H, HW = H * W;
    float Nf = (float)HW;
    float s5part = 0.f;
    for (int c = threadIdx.x; c < C; c += THREADS) {
        int ch = cb + c;
        int gg[6], sg = 0;
#pragma unroll
        for (int j = 0; j < 5; j++) { gg[j] = g_hist[ch][6 + j]; sg += gg[j]; }
        gg[5] = HW - sg;                      // all non-rare interior pixels have gidx 5

        float hv[6];
#pragma unroll
        for (int j = 0; j < 6; j++)
            hv[j] = -logf(__fdiv_rn((float)g_hist[ch][j], Nf) + 1e-4f);

        float minv = 1e30f, maxv = -1e30f;
#pragma unroll
        for (int j = 0; j < 6; j++)
            if (gg[j] > 0) { minv = fminf(minv, hv[j]); maxv = fmaxf(maxv, hv[j]); }
        float rh = maxv - minv;

        const int jb = 0;                      // border pixels (value 0) -> gidx bin 0
        bool first = (c == 0);                 // channel 0 keeps its border in the map

        float lut[6] = {0.f, 0.f, 0.f, 0.f, 0.f, 0.f};
        if (rh > 0.f) {
            float dn[6];
#pragma unroll
            for (int j = 0; j < 6; j++)
                dn[j] = (gg[j] > 0) ? __fdiv_rn(hv[j] - minv, rh) : 0.f;
            float meandn = 0.f;
#pragma unroll
            for (int j = 0; j < 6; j++) meandn += (float)gg[j] * dn[j];
            meandn = __fdiv_rn(meandn, Nf);
            float w1 = 1.f - meandn; w1 *= w1;     // (max_dst - mean_dst)^2
            int Nb = 2 * (H + W) - 4;
            float mean_m = 0.f;
            float max_m = first ? -1e30f : 0.f;    // zeroed border contributes 0 for c>=1
#pragma unroll
            for (int j = 0; j < 6; j++) {
                int cnt = gg[j] - ((!first && j == jb) ? Nb : 0);
                float rv = dn[j] * w1;
                if (cnt > 0) { mean_m += (float)cnt * rv; max_m = fmaxf(max_m, rv); }
            }
            mean_m = __fdiv_rn(mean_m, Nf);
            if (max_m > 0.f) {
                float w2 = max_m - mean_m; w2 *= w2;   // min_m == 0 always
#pragma unroll
                for (int j = 0; j < 6; j++)
                    lut[j] = __fmul_rn(__fdiv_rn(dn[j] * w1, max_m), w2);
            }
        }
#pragma unroll
        for (int j = 0; j < 6; j++) g_lut[ch][j] = lut[j];
        s5part += lut[5];
        if (c == 0) sbord = lut[jb];
    }
    sh[threadIdx.x] = s5part;
    __syncthreads();
    for (int st = THREADS / 2; st; st >>= 1) {
        if (threadIdx.x < st) sh[threadIdx.x] += sh[threadIdx.x + st];
        __syncthreads();
    }
    if (threadIdx.x == 0) { g_S5[blockIdx.x] = sh[0]; g_bord[blockIdx.x] = sbord; }
}

// ---------------- pass scatter: apply rare corrections into zeroed g_proc ----------------
__global__ void __launch_bounds__(THREADS) k_scatter() {
    unsigned n = g_rarecnt;
    for (unsigned i = blockIdx.x * THREADS + threadIdx.x; i < n; i += gridDim.x * THREADS) {
        unsigned e = g_rare[i];
        unsigned pix = e & 0x3FFFFu;
        unsigned ch  = (e >> 18) & 0x7FFu;
        unsigned b2  = e >> 29;
        int layer = ch < 64 ? 0 : ch < 192 ? 1 : ch < 448 ? 2 : ch < 960 ? 3 : 4;
        float d = g_lut[ch][b2] - g_lut[ch][5];
        atomicAdd(&g_proc[c_procBase[layer] + pix], d);
    }
}

// ---------------- pass pstat: add base (S5/bord), write true proc, min/max ----------------
__global__ void __launch_bounds__(THREADS) k_pstat() {
    __shared__ float sred[16];
    int b = blockIdx.x;
    int layer, loc;
    if (b < 900)       { layer = 0; loc = b; }
    else if (b < 1125) { layer = 1; loc = b - 900; }
    else if (b < 1182) { layer = 2; loc = b - 1125; }
    else if (b < 1197) { layer = 3; loc = b - 1182; }
    else               { layer = 4; loc = b - 1197; }
    int W = c_H[layer], HW = W * W, pb = c_procBase[layer];
    int p = loc * THREADS + threadIdx.x;
    float vmn = 1e30f, vmx = -1e30f;
    if (p < HW) {
        int r = p / W, c = p - r * W;
        bool bd = (r == 0) | (c == 0) | (r == W - 1) | (c == W - 1);
        float base = bd ? g_bord[layer] : g_S5[layer];
        float val = base + g_proc[pb + p];
        g_proc[pb + p] = val;
        vmn = val; vmx = val;
    }
    blockMinMax(vmn, vmx, g_pstat[layer], sred);
}

// ---------------- pass E: normalize+threshold (fused) + resize + group min/max ----
__device__ __forceinline__ float fth(float v, float mnp, float rng) {
    float pn = (rng == 0.f) ? 0.f : __fdiv_rn(v - mnp, rng);
    return (pn < 0.2f) ? 0.f : pn;
}

__global__ void __launch_bounds__(THREADS) k_resize() {
    __shared__ float sred[16];
    int b = blockIdx.x;
    int layer = b / 225;
    int p = (b - layer * 225) * THREADS + threadIdx.x;   // < 57600 exactly
    int y = p / 240, x = p % 240;
    float mnp = fdec(g_pstat[layer][0]);
    float mxp = fdec(g_pstat[layer][1]);
    float rng = mxp - mnp;
    float val;
    if (layer == 0) {
        // 480 -> 240 antialiased: taps [1,3,3,1]/8, edge-renormalized
        const float w4[4] = {1.f, 3.f, 3.f, 1.f};
        float wxs = 0.f;
#pragma unroll
        for (int j = 0; j < 4; j++) { int tx = 2 * x - 1 + j; if (tx >= 0 && tx < 480) wxs += w4[j]; }
        float acc = 0.f, wys = 0.f;
#pragma unroll
        for (int a = 0; a < 4; a++) {
            int ty = 2 * y - 1 + a;
            if (ty < 0 || ty > 479) continue;
            wys += w4[a];
            const float* row = g_proc + ty * 480;
            float ra = 0.f;
#pragma unroll
            for (int j = 0; j < 4; j++) {
                int tx = 2 * x - 1 + j;
                if (tx >= 0 && tx < 480) ra += w4[j] * fth(row[tx], mnp, rng);
            }
            acc += w4[a] * ra;
        }
        val = acc / (wys * wxs);
    } else if (layer == 1) {
        val = fth(g_proc[230400 + p], mnp, rng);         // identity resize
    } else {
        int H = layer == 2 ? 120 : layer == 3 ? 60 : 30;
        int base = layer == 2 ? 288000 : layer == 3 ? 302400 : 306000;
        const float* pr = g_proc + base;
        float s = (float)H / 240.f;                      // 0.5 / 0.25 / 0.125 exact
        float cy = (y + 0.5f) * s - 0.5f;
        float cx = (x + 0.5f) * s - 0.5f;
        float fly = floorf(cy), flx = floorf(cx);
        float fy = cy - fly, fx = cx - flx;
        int iy = (int)fly, ix = (int)flx;
        int y0 = max(iy, 0), y1 = min(iy + 1, H - 1);
        int x0 = max(ix, 0), x1 = min(ix + 1, H - 1);
        float a = fth(pr[y0 * H + x0], mnp, rng), bv = fth(pr[y0 * H + x1], mnp, rng);
        float c = fth(pr[y1 * H + x0], mnp, rng), d = fth(pr[y1 * H + x1], mnp, rng);
        val = (1.f - fy) * ((1.f - fx) * a + fx * bv) + fy * ((1.f - fx) * c + fx * d);
    }
    g_group[layer][p] = val;
    blockMinMax(val, val, g_gstat[layer], sred);
}

// ---------------- pass F: group normalize(0,256), write groups + sum ----------------
__global__ void __launch_bounds__(THREADS) k_final(float* __restrict__ out, int out_size) {
    int p = blockIdx.x * THREADS + threadIdx.x;          // 225 blocks * 256 = 57600 exactly
    float s = 0.f;
#pragma unroll
    for (int g = 0; g < 5; g++) {
        float mn = fdec(g_gstat[g][0]);
        float mx = fdec(g_gstat[g][1]);
        float rng = mx - mn;
        float v = g_group[g][p];
        float gv = (rng == 0.f) ? 0.f : __fmul_rn(__fdiv_rn(v - mn, rng), 256.f);
        if (out_size >= 345600) out[57600 + p * 5 + g] = gv;
        s += gv;
    }
    out[p] = s;
}

// ---------------- launch ----------------
extern "C" void kernel_launch(void* const* d_in, const int* in_sizes, int n_in,
                              void* d_out, int out_size) {
    const int want[5] = {14745600, 7372800, 3686400, 1843200, 460800};
    const float* L[5] = {nullptr, nullptr, nullptr, nullptr, nullptr};
    for (int i = 0; i < n_in && i < 16; i++)
        for (int j = 0; j < 5; j++)
            if (in_sizes[i] == want[j] && L[j] == nullptr) { L[j] = (const float*)d_in[i]; break; }
    for (int j = 0; j < 5; j++) if (!L[j] && j < n_in) L[j] = (const float*)d_in[j];

    k_init<<<1199, THREADS>>>();
    k_maxhist<<<4608, THREADS>>>(L[0], L[1], L[2], L[3], L[4]);
    k_lut_s5<<<5, THREADS>>>();
    k_scatter<<<592, THREADS>>>();
    k_pstat<<<1201, THREADS>>>();
    k_resize<<<1125, THREADS>>>();
    k_final<<<225, THREADS>>>((float*)d_out, out_size);
}